// round 4
// baseline (speedup 1.0000x reference)
#include <cuda_runtime.h>
#include <cuda_bf16.h>
#include <cstdint>
#include <cstddef>

// ============================================================================
// Problem constants
// ============================================================================
#define NROWS  65536
#define DDIM   128
#define KCB    2048
#define DHALF  64

#define TILE_M   128               // z rows per main-kernel block
#define CHUNK_N  128               // emb columns per chunk
#define NCHUNKS  (KCB / CHUNK_N)   // 16
#define NTILES   (NROWS / TILE_M)  // 512

// ============================================================================
// Device scratch (allocation-free rule: __device__ globals)
// ============================================================================
__device__ __nv_bfloat16 g_Zh[(size_t)NROWS * DHALF];
__device__ __nv_bfloat16 g_Zm[(size_t)NROWS * DHALF];
__device__ __nv_bfloat16 g_Zl[(size_t)NROWS * DHALF];
__device__ __nv_bfloat16 g_Eh[KCB * DHALF];
__device__ __nv_bfloat16 g_Em[KCB * DHALF];
__device__ __nv_bfloat16 g_El[KCB * DHALF];
__device__ float g_c[KCB];        // ||emb_k||^2 in projected space
__device__ float g_zz[NROWS];     // ||z_n||^2  in projected space

// ============================================================================
// PTX helpers (generic sm_80+ PTX only — NO tcgen05 on this build's target)
// ============================================================================
__device__ __forceinline__ uint32_t smem_u32(const void* p) {
    uint32_t a;
    asm("{ .reg .u64 t; cvta.to.shared.u64 t, %1; cvt.u32.u64 %0, t; }"
        : "=r"(a) : "l"(p));
    return a;
}

__device__ __forceinline__ uint32_t sw128(uint32_t x) { return x ^ ((x >> 3) & 0x70); }

__device__ __forceinline__ void cp_async16(uint32_t dst, const void* src) {
    asm volatile("cp.async.cg.shared.global [%0], [%1], 16;" :: "r"(dst), "l"(src));
}
#define CP_COMMIT()  asm volatile("cp.async.commit_group;" ::: "memory")
#define CP_WAIT(n)   asm volatile("cp.async.wait_group %0;" :: "n"(n) : "memory")

__device__ __forceinline__ void ldsm_x4(uint32_t* r, uint32_t addr) {
    asm volatile("ldmatrix.sync.aligned.m8n8.x4.shared.b16 {%0,%1,%2,%3}, [%4];"
        : "=r"(r[0]), "=r"(r[1]), "=r"(r[2]), "=r"(r[3]) : "r"(addr));
}

__device__ __forceinline__ void mma_bf16(float* c, const uint32_t* a,
                                         uint32_t b0, uint32_t b1) {
    asm volatile(
        "mma.sync.aligned.m16n8k16.row.col.f32.bf16.bf16.f32 "
        "{%0,%1,%2,%3}, {%4,%5,%6,%7}, {%8,%9}, {%0,%1,%2,%3};"
        : "+f"(c[0]), "+f"(c[1]), "+f"(c[2]), "+f"(c[3])
        : "r"(a[0]), "r"(a[1]), "r"(a[2]), "r"(a[3]), "r"(b0), "r"(b1));
}

// ============================================================================
// Prep kernel: projects 64 rows of X by W^T + b (fp32), emits 3-way bf16 split
// and row squared-norms (deterministic butterfly reduction, no atomics).
// ============================================================================
#define PREP_SMEM ((2 * 64 * 129 + 64) * 4)

__global__ void __launch_bounds__(256) prep_kernel(const float* __restrict__ X,
                                                   const float* __restrict__ W,
                                                   const float* __restrict__ b,
                                                   int is_emb) {
    extern __shared__ float sm[];
    float* Xs = sm;                  // [64][129]
    float* Ws = sm + 64 * 129;       // [64][129]
    float* bs = sm + 2 * 64 * 129;   // [64]
    const int tid = threadIdx.x;
    const int row0 = blockIdx.x * 64;

    for (int i = tid; i < 64 * 128; i += 256) {
        int r = i >> 7, d = i & 127;
        Xs[r * 129 + d] = X[(size_t)(row0 + r) * DDIM + d];
        Ws[r * 129 + d] = W[i];
    }
    if (tid < 64) bs[tid] = b[tid];
    __syncthreads();

    const int tx = tid & 15, ty = tid >> 4;
    const int r0 = ty * 4, h0 = tx * 4;
    float acc[4][4];
#pragma unroll
    for (int i = 0; i < 4; i++)
#pragma unroll
        for (int j = 0; j < 4; j++) acc[i][j] = bs[h0 + j];

    for (int d = 0; d < DDIM; ++d) {
        float a[4], w[4];
#pragma unroll
        for (int i = 0; i < 4; i++) a[i] = Xs[(r0 + i) * 129 + d];
#pragma unroll
        for (int j = 0; j < 4; j++) w[j] = Ws[(h0 + j) * 129 + d];
#pragma unroll
        for (int i = 0; i < 4; i++)
#pragma unroll
            for (int j = 0; j < 4; j++) acc[i][j] = fmaf(a[i], w[j], acc[i][j]);
    }

    __nv_bfloat16* Oh = is_emb ? g_Eh : g_Zh;
    __nv_bfloat16* Om = is_emb ? g_Em : g_Zm;
    __nv_bfloat16* Ol = is_emb ? g_El : g_Zl;
    float* cOut = is_emb ? g_c : g_zz;

    // per-thread partial row norms over the 4 owned cols
    float pn[4];
#pragma unroll
    for (int i = 0; i < 4; i++) {
        pn[i] = 0.0f;
#pragma unroll
        for (int j = 0; j < 4; j++) pn[i] = fmaf(acc[i][j], acc[i][j], pn[i]);
    }
    // butterfly across the 16 tx lanes (stays within 16-lane half-warp)
#pragma unroll
    for (int off = 1; off < 16; off <<= 1)
#pragma unroll
        for (int i = 0; i < 4; i++)
            pn[i] += __shfl_xor_sync(0xffffffffu, pn[i], off);
    if (tx == 0)
#pragma unroll
        for (int i = 0; i < 4; i++) cOut[row0 + r0 + i] = pn[i];

#pragma unroll
    for (int i = 0; i < 4; i++)
#pragma unroll
        for (int j = 0; j < 4; j++) {
            float v = acc[i][j];
            __nv_bfloat16 h = __float2bfloat16(v);
            float fh = __bfloat162float(h);
            __nv_bfloat16 m = __float2bfloat16(v - fh);
            float fm = __bfloat162float(m);
            __nv_bfloat16 l = __float2bfloat16((v - fh) - fm);
            size_t o = (size_t)(row0 + r0 + i) * DHALF + (h0 + j);
            Oh[o] = h; Om[o] = m; Ol[o] = l;
        }
}

// ============================================================================
// Main kernel: per 128-row tile, S = Z~ @ E~^T via 6 split products fused as a
// K=384 bf16 HMMA GEMM (mma.sync m16n8k16), fused per-row argmin epilogue,
// one-hot write (full rows, no memset), quantized gather.
//
// dynamic smem layout (bytes):
//   0:      red_d[128][4] float       (2048)
//   2048:   red_i[128][4] int         (2048)
//   4096:   args[128] int             (512)
//   4608:   zz_s[128] float           (512)
//   5120:   cs[2048] float            (8192)   -> 13312
//   14336:  A tiles 3 x 16384         -> 63488  (1KB aligned)
//   63488:  B bufs  2 x 3 x 16384     -> 161792
// ============================================================================
#define RED_D_OFF 0u
#define RED_I_OFF 2048u
#define ARGS_OFF  4096u
#define ZZ_OFF    4608u
#define CS_OFF    5120u
#define A_OFF     14336u
#define B_OFF     63488u
#define MAIN_SMEM 161792

__device__ __forceinline__ void load_B_chunk(uint32_t sb, int chunk, int buf, int tid) {
    const __nv_bfloat16* srcs[3] = {g_Eh, g_Em, g_El};
#pragma unroll
    for (int s = 0; s < 3; ++s) {
        const char* src = (const char*)srcs[s] + (size_t)chunk * CHUNK_N * 128;  // 128B rows
        uint32_t dstbase = sb + B_OFF + (uint32_t)(buf * 3 + s) * 16384u;
        for (int i = tid; i < 1024; i += 256) {
            uint32_t off = (uint32_t)(i >> 3) * 128u + (uint32_t)(i & 7) * 16u;
            cp_async16(dstbase + sw128(off), src + off);
        }
    }
}

__global__ void __launch_bounds__(256, 1)
vq_main_kernel(const float* __restrict__ emb,
               float* __restrict__ outQ, float* __restrict__ outOH) {
    extern __shared__ char smem[];
    const uint32_t sb = smem_u32(smem);
    const int tid  = threadIdx.x;
    const int lane = tid & 31;
    const int wid  = tid >> 5;
    const int wm   = wid >> 2;           // 0..1  (rows)
    const int wn   = wid & 3;            // 0..3  (cols)
    const int row0 = blockIdx.x * TILE_M;

    float* red_d = (float*)(smem + RED_D_OFF);
    int*   red_i = (int*)  (smem + RED_I_OFF);
    int*   args  = (int*)  (smem + ARGS_OFF);
    float* zz_s  = (float*)(smem + ZZ_OFF);
    float* cs    = (float*)(smem + CS_OFF);

    for (int i = tid; i < KCB; i += 256) cs[i] = g_c[i];
    if (tid < 128) zz_s[tid] = g_zz[row0 + tid];

    // A tiles (3 splits of the 128-row z~ tile), SW128 swizzled, resident
    {
        const __nv_bfloat16* srcs[3] = {g_Zh, g_Zm, g_Zl};
#pragma unroll
        for (int s = 0; s < 3; ++s) {
            const char* src = (const char*)srcs[s] + (size_t)row0 * 128;  // 128B rows
            uint32_t dstbase = sb + A_OFF + (uint32_t)s * 16384u;
            for (int i = tid; i < 1024; i += 256) {
                uint32_t off = (uint32_t)(i >> 3) * 128u + (uint32_t)(i & 7) * 16u;
                cp_async16(dstbase + sw128(off), src + off);
            }
        }
    }
    load_B_chunk(sb, 0, 0, tid);
    CP_COMMIT();
    CP_WAIT(0);
    __syncthreads();

    // ldmatrix lane geometry (shared by A and B)
    const uint32_t r8     = (uint32_t)((lane & 7) + 8 * ((lane >> 3) & 1)); // row in 16-grp
    const uint32_t xm     = (uint32_t)(lane & 7) * 16u;                     // swizzle xor
    const uint32_t colSel = (uint32_t)((lane >> 4) & 1) * 16u;              // k half (16B)

    uint32_t aRow[4], bRow[2];
#pragma unroll
    for (int mt = 0; mt < 4; ++mt)
        aRow[mt] = (uint32_t)(wm * 64 + mt * 16) * 128u + r8 * 128u;
#pragma unroll
    for (int ng = 0; ng < 2; ++ng)
        bRow[ng] = (uint32_t)(wn * 32 + ng * 16) * 128u + r8 * 128u;

    // per-lane zz for the 8 owned rows: row = wm*64 + mt*16 + lane/4 (+8)
    float zzv[4][2];
#pragma unroll
    for (int mt = 0; mt < 4; ++mt) {
        zzv[mt][0] = zz_s[wm * 64 + mt * 16 + (lane >> 2)];
        zzv[mt][1] = zz_s[wm * 64 + mt * 16 + (lane >> 2) + 8];
    }

    float acc[4][4][4];
#pragma unroll
    for (int mt = 0; mt < 4; ++mt)
#pragma unroll
        for (int nt = 0; nt < 4; ++nt)
#pragma unroll
            for (int q = 0; q < 4; ++q) acc[mt][nt][q] = 0.0f;

    // running argmin state: 8 row-slots per lane (mt x {lo,hi})
    float bestd[4][2];
    int   besti[4][2];
#pragma unroll
    for (int mt = 0; mt < 4; ++mt)
#pragma unroll
        for (int h = 0; h < 2; ++h) {
            bestd[mt][h] = __int_as_float(0x7f800000);
            besti[mt][h] = 0;
        }

    const int PA[6] = {0, 0, 1, 1, 0, 2};
    const int PB[6] = {0, 1, 0, 1, 2, 0};

    for (int chunk = 0; chunk < NCHUNKS; ++chunk) {
        const int buf = chunk & 1;
        // prefetch next B chunk into the other buffer (freed by prev-iter sync)
        if (chunk + 1 < NCHUNKS) load_B_chunk(sb, chunk + 1, buf ^ 1, tid);
        CP_COMMIT();
        if (chunk + 1 < NCHUNKS) CP_WAIT(1); else CP_WAIT(0);
        __syncthreads();

        // ---- GEMM: 6 split products x 4 k-tiles over this 128-col chunk ----
#pragma unroll
        for (int p = 0; p < 6; ++p) {
            const uint32_t aB = sb + A_OFF + (uint32_t)PA[p] * 16384u;
            const uint32_t bB = sb + B_OFF + (uint32_t)(buf * 3 + PB[p]) * 16384u;
#pragma unroll
            for (int kt = 0; kt < 4; ++kt) {
                const uint32_t kc = ((uint32_t)(kt * 32) + colSel) ^ xm;
                uint32_t afr[4][4];
#pragma unroll
                for (int mt = 0; mt < 4; ++mt) ldsm_x4(afr[mt], aB + aRow[mt] + kc);
                uint32_t bfr[2][4];
#pragma unroll
                for (int ng = 0; ng < 2; ++ng) ldsm_x4(bfr[ng], bB + bRow[ng] + kc);
#pragma unroll
                for (int mt = 0; mt < 4; ++mt)
#pragma unroll
                    for (int nt = 0; nt < 4; ++nt)
                        mma_bf16(acc[mt][nt], afr[mt],
                                 bfr[nt >> 1][nt & 1], bfr[nt >> 1][(nt & 1) + 2]);
            }
        }

        // ---- fused argmin epilogue for this chunk, then reset acc ----
        const int colbase = chunk * CHUNK_N + wn * 32 + 2 * (lane & 3);
#pragma unroll
        for (int mt = 0; mt < 4; ++mt) {
#pragma unroll
            for (int nt = 0; nt < 4; ++nt) {
                const int c0 = colbase + nt * 8;
                const float cv0 = cs[c0], cv1 = cs[c0 + 1];
#pragma unroll
                for (int h = 0; h < 2; ++h) {
                    // match reference fp32 op order: (zz + c) - 2*s
                    float d0 = __fsub_rn(__fadd_rn(zzv[mt][h], cv0),
                                         __fmul_rn(2.0f, acc[mt][nt][2 * h + 0]));
                    float d1 = __fsub_rn(__fadd_rn(zzv[mt][h], cv1),
                                         __fmul_rn(2.0f, acc[mt][nt][2 * h + 1]));
                    // ascending-index scan: strict < keeps first-min index
                    besti[mt][h] = (d0 < bestd[mt][h]) ? c0 : besti[mt][h];
                    bestd[mt][h] = fminf(bestd[mt][h], d0);
                    besti[mt][h] = (d1 < bestd[mt][h]) ? (c0 + 1) : besti[mt][h];
                    bestd[mt][h] = fminf(bestd[mt][h], d1);
                    acc[mt][nt][2 * h + 0] = 0.0f;
                    acc[mt][nt][2 * h + 1] = 0.0f;
                }
            }
        }

        __syncthreads();   // compute done before next iter overwrites buf
    }

    // ---- cross-lane / cross-warp argmin reduction ----
#pragma unroll
    for (int mt = 0; mt < 4; ++mt)
#pragma unroll
        for (int h = 0; h < 2; ++h) {
            float d = bestd[mt][h];
            int   i = besti[mt][h];
#pragma unroll
            for (int off = 1; off < 4; off <<= 1) {
                float od = __shfl_xor_sync(0xffffffffu, d, off);
                int   oi = __shfl_xor_sync(0xffffffffu, i, off);
                if (od < d || (od == d && oi < i)) { d = od; i = oi; }
            }
            if ((lane & 3) == 0) {
                int row = wm * 64 + mt * 16 + (lane >> 2) + 8 * h;
                red_d[row * 4 + wn] = d;
                red_i[row * 4 + wn] = i;
            }
        }
    __syncthreads();

    if (tid < 128) {
        float bd = red_d[tid * 4 + 0];
        int   bi = red_i[tid * 4 + 0];
#pragma unroll
        for (int w = 1; w < 4; ++w) {
            float d = red_d[tid * 4 + w];
            int   i = red_i[tid * 4 + w];
            if (d < bd || (d == bd && i < bi)) { bd = d; bi = i; }
        }
        args[tid] = bi;
    }
    __syncthreads();

    // ---- one-hot: write full rows (region is NOT pre-zeroed) ----
    for (int i = tid; i < 128 * (KCB / 4); i += 256) {
        int r  = i >> 9;          // /512
        int c4 = i & 511;
        float4 v = make_float4(0.f, 0.f, 0.f, 0.f);
        int a = args[r];
        if ((a >> 2) == c4) ((float*)&v)[a & 3] = 1.0f;
        ((float4*)(outOH + (size_t)(row0 + r) * KCB))[c4] = v;
    }

    // ---- quantized gather: 128 rows x 32 float4 ----
    {
        const float4* e4 = (const float4*)emb;
        float4* q4 = (float4*)outQ;
        for (int i = tid; i < 128 * 32; i += 256) {
            int r = i >> 5, c = i & 31;
            q4[(size_t)(row0 + r) * 32 + c] = e4[(size_t)args[r] * 32 + c];
        }
    }
}

// ============================================================================
// Launch
// ============================================================================
extern "C" void kernel_launch(void* const* d_in, const int* in_sizes, int n_in,
                              void* d_out, int out_size) {
    const float* z   = (const float*)d_in[0];
    const float* W   = (const float*)d_in[1];
    const float* b   = (const float*)d_in[2];
    const float* emb = (const float*)d_in[3];

    float* outQ  = (float*)d_out;                 // [N, 128]
    float* outOH = outQ + (size_t)NROWS * DDIM;   // [N, 2048]

    cudaFuncSetAttribute(prep_kernel, cudaFuncAttributeMaxDynamicSharedMemorySize, PREP_SMEM);
    cudaFuncSetAttribute(vq_main_kernel, cudaFuncAttributeMaxDynamicSharedMemorySize, MAIN_SMEM);

    prep_kernel<<<KCB / 64, 256, PREP_SMEM>>>(emb, W, b, 1);
    prep_kernel<<<NROWS / 64, 256, PREP_SMEM>>>(z, W, b, 0);
    vq_main_kernel<<<NTILES, 256, MAIN_SMEM>>>(emb, outQ, outOH);
}

// round 5
// speedup vs baseline: 1.5202x; 1.5202x over previous
#include <cuda_runtime.h>
#include <cuda_bf16.h>
#include <cuda_fp16.h>
#include <cstdint>
#include <cstddef>

// ============================================================================
// Problem constants
// ============================================================================
#define NROWS  65536
#define DDIM   128
#define KCB    2048
#define DHALF  64

#define TILE_M   128               // z rows per main-kernel block
#define CHUNK_N  128               // emb columns per chunk
#define NCHUNKS  (KCB / CHUNK_N)   // 16
#define NTILES   (NROWS / TILE_M)  // 512

// ============================================================================
// Device scratch (allocation-free rule: __device__ globals)
// fp16 2-way split: v = h + r (+ eps ~2^-23 |v|)
// ============================================================================
__device__ __half g_Zh[(size_t)NROWS * DHALF];
__device__ __half g_Zr[(size_t)NROWS * DHALF];
__device__ __half g_Eh[KCB * DHALF];
__device__ __half g_Er[KCB * DHALF];
__device__ float  g_c[KCB];        // ||emb_k||^2 in projected space
__device__ float  g_zz[NROWS];     // ||z_n||^2  in projected space

// ============================================================================
// PTX helpers (generic sm_80+ PTX only — tcgen05 not available on this target)
// ============================================================================
__device__ __forceinline__ uint32_t smem_u32(const void* p) {
    uint32_t a;
    asm("{ .reg .u64 t; cvta.to.shared.u64 t, %1; cvt.u32.u64 %0, t; }"
        : "=r"(a) : "l"(p));
    return a;
}

__device__ __forceinline__ uint32_t sw128(uint32_t x) { return x ^ ((x >> 3) & 0x70); }

__device__ __forceinline__ void cp_async16(uint32_t dst, const void* src) {
    asm volatile("cp.async.cg.shared.global [%0], [%1], 16;" :: "r"(dst), "l"(src));
}
#define CP_COMMIT()  asm volatile("cp.async.commit_group;" ::: "memory")
#define CP_WAIT(n)   asm volatile("cp.async.wait_group %0;" :: "n"(n) : "memory")

__device__ __forceinline__ void ldsm_x4(uint32_t* r, uint32_t addr) {
    asm volatile("ldmatrix.sync.aligned.m8n8.x4.shared.b16 {%0,%1,%2,%3}, [%4];"
        : "=r"(r[0]), "=r"(r[1]), "=r"(r[2]), "=r"(r[3]) : "r"(addr));
}

__device__ __forceinline__ void mma_f16(float* c, const uint32_t* a,
                                        uint32_t b0, uint32_t b1) {
    asm volatile(
        "mma.sync.aligned.m16n8k16.row.col.f32.f16.f16.f32 "
        "{%0,%1,%2,%3}, {%4,%5,%6,%7}, {%8,%9}, {%0,%1,%2,%3};"
        : "+f"(c[0]), "+f"(c[1]), "+f"(c[2]), "+f"(c[3])
        : "r"(a[0]), "r"(a[1]), "r"(a[2]), "r"(a[3]), "r"(b0), "r"(b1));
}

// ============================================================================
// Prep kernel: projects 64 rows of X by W^T + b (fp32), emits fp16 2-way split
// and row squared-norms (deterministic butterfly reduction).
// float4-vectorized k loop; cols owned strided (tx, tx+16, tx+32, tx+48).
// ============================================================================
#define PREP_PAD   132                               // floats per smem row (16B aligned, odd float4 stride)
#define PREP_SMEM  ((2 * 64 * PREP_PAD + 64) * 4)

__global__ void __launch_bounds__(256) prep_kernel(const float* __restrict__ X,
                                                   const float* __restrict__ W,
                                                   const float* __restrict__ b,
                                                   int is_emb) {
    extern __shared__ float sm[];
    float* Xs = sm;                        // [64][PREP_PAD]
    float* Ws = sm + 64 * PREP_PAD;        // [64][PREP_PAD]
    float* bs = sm + 2 * 64 * PREP_PAD;    // [64]
    const int tid = threadIdx.x;
    const int row0 = blockIdx.x * 64;

    for (int i = tid; i < 64 * 32; i += 256) {   // float4 granularity
        int r = i >> 5, d4 = i & 31;
        ((float4*)(Xs + r * PREP_PAD))[d4] = ((const float4*)(X + (size_t)(row0 + r) * DDIM))[d4];
        ((float4*)(Ws + r * PREP_PAD))[d4] = ((const float4*)(W + (size_t)r * DDIM))[d4];
    }
    if (tid < 64) bs[tid] = b[tid];
    __syncthreads();

    const int tx = tid & 15, ty = tid >> 4;
    const int r0 = ty * 4;                 // 4 consecutive rows
    // cols owned: c = tx + 16*j
    float acc[4][4];
#pragma unroll
    for (int i = 0; i < 4; i++)
#pragma unroll
        for (int j = 0; j < 4; j++) acc[i][j] = bs[tx + 16 * j];

    const float4* Xs4 = (const float4*)Xs;   // row stride 33 float4
    const float4* Ws4 = (const float4*)Ws;
#pragma unroll 8
    for (int d4 = 0; d4 < 32; ++d4) {
        float4 a4[4], w4[4];
#pragma unroll
        for (int i = 0; i < 4; i++) a4[i] = Xs4[(r0 + i) * 33 + d4];
#pragma unroll
        for (int j = 0; j < 4; j++) w4[j] = Ws4[(tx + 16 * j) * 33 + d4];
#pragma unroll
        for (int i = 0; i < 4; i++)
#pragma unroll
            for (int j = 0; j < 4; j++) {
                acc[i][j] = fmaf(a4[i].x, w4[j].x, acc[i][j]);
                acc[i][j] = fmaf(a4[i].y, w4[j].y, acc[i][j]);
                acc[i][j] = fmaf(a4[i].z, w4[j].z, acc[i][j]);
                acc[i][j] = fmaf(a4[i].w, w4[j].w, acc[i][j]);
            }
    }

    __half* Oh = is_emb ? g_Eh : g_Zh;
    __half* Or = is_emb ? g_Er : g_Zr;
    float* cOut = is_emb ? g_c : g_zz;

    // per-thread partial row norms over the 4 owned cols
    float pn[4];
#pragma unroll
    for (int i = 0; i < 4; i++) {
        pn[i] = 0.0f;
#pragma unroll
        for (int j = 0; j < 4; j++) pn[i] = fmaf(acc[i][j], acc[i][j], pn[i]);
    }
    // butterfly across the 16 tx lanes (within 16-lane half-warp)
#pragma unroll
    for (int off = 1; off < 16; off <<= 1)
#pragma unroll
        for (int i = 0; i < 4; i++)
            pn[i] += __shfl_xor_sync(0xffffffffu, pn[i], off);
    if (tx == 0)
#pragma unroll
        for (int i = 0; i < 4; i++) cOut[row0 + r0 + i] = pn[i];

#pragma unroll
    for (int i = 0; i < 4; i++)
#pragma unroll
        for (int j = 0; j < 4; j++) {
            float v = acc[i][j];
            __half h = __float2half_rn(v);
            __half r = __float2half_rn(v - __half2float(h));
            size_t o = (size_t)(row0 + r0 + i) * DHALF + (tx + 16 * j);
            Oh[o] = h; Or[o] = r;
        }
}

// ============================================================================
// Main kernel: per 128-row tile, S = Z~ @ E~^T via 3 fp16 split products
// (hh, hr, rh) fused as a K=192 HMMA GEMM, fused per-row argmin epilogue,
// one-hot write (full rows, streaming), quantized gather.
//
// dynamic smem (bytes):
//   0:      red_d[128][4] f32  (2048)
//   2048:   red_i[128][4] i32  (2048)
//   4096:   args[128] i32      (512)
//   4608:   zz_s[128] f32      (512)
//   5120:   cs[2048] f32       (8192)  -> 13312
//   14336:  A tiles 2 x 16384  -> 47104
//   47104:  B bufs  2 x 2 x 16384 -> 112640
// ============================================================================
#define RED_D_OFF 0u
#define RED_I_OFF 2048u
#define ARGS_OFF  4096u
#define ZZ_OFF    4608u
#define CS_OFF    5120u
#define A_OFF     14336u
#define B_OFF     47104u
#define MAIN_SMEM 112640

__device__ __forceinline__ void load_B_chunk(uint32_t sb, int chunk, int buf, int tid) {
    const __half* srcs[2] = {g_Eh, g_Er};
#pragma unroll
    for (int s = 0; s < 2; ++s) {
        const char* src = (const char*)srcs[s] + (size_t)chunk * CHUNK_N * 128;  // 128B rows
        uint32_t dstbase = sb + B_OFF + (uint32_t)(buf * 2 + s) * 16384u;
        for (int i = tid; i < 1024; i += 256) {
            uint32_t off = (uint32_t)(i >> 3) * 128u + (uint32_t)(i & 7) * 16u;
            cp_async16(dstbase + sw128(off), src + off);
        }
    }
}

__global__ void __launch_bounds__(256, 2)
vq_main_kernel(const float* __restrict__ emb,
               float* __restrict__ outQ, float* __restrict__ outOH) {
    extern __shared__ char smem[];
    const uint32_t sb = smem_u32(smem);
    const int tid  = threadIdx.x;
    const int lane = tid & 31;
    const int wid  = tid >> 5;
    const int wm   = wid >> 2;           // 0..1  (rows)
    const int wn   = wid & 3;            // 0..3  (cols)
    const int row0 = blockIdx.x * TILE_M;

    float* red_d = (float*)(smem + RED_D_OFF);
    int*   red_i = (int*)  (smem + RED_I_OFF);
    int*   args  = (int*)  (smem + ARGS_OFF);
    float* zz_s  = (float*)(smem + ZZ_OFF);
    float* cs    = (float*)(smem + CS_OFF);

    for (int i = tid; i < KCB; i += 256) cs[i] = g_c[i];
    if (tid < 128) zz_s[tid] = g_zz[row0 + tid];

    // A tiles (2 fp16 splits of the 128-row z~ tile), SW128 swizzled, resident
    {
        const __half* srcs[2] = {g_Zh, g_Zr};
#pragma unroll
        for (int s = 0; s < 2; ++s) {
            const char* src = (const char*)srcs[s] + (size_t)row0 * 128;  // 128B rows
            uint32_t dstbase = sb + A_OFF + (uint32_t)s * 16384u;
            for (int i = tid; i < 1024; i += 256) {
                uint32_t off = (uint32_t)(i >> 3) * 128u + (uint32_t)(i & 7) * 16u;
                cp_async16(dstbase + sw128(off), src + off);
            }
        }
    }
    load_B_chunk(sb, 0, 0, tid);
    CP_COMMIT();
    CP_WAIT(0);
    __syncthreads();

    // ldmatrix lane geometry (shared by A and B)
    const uint32_t r8     = (uint32_t)((lane & 7) + 8 * ((lane >> 3) & 1)); // row in 16-grp
    const uint32_t xm     = (uint32_t)(lane & 7) * 16u;                     // swizzle xor
    const uint32_t colSel = (uint32_t)((lane >> 4) & 1) * 16u;              // k half (16B)

    uint32_t aRow[4], bRow[2];
#pragma unroll
    for (int mt = 0; mt < 4; ++mt)
        aRow[mt] = (uint32_t)(wm * 64 + mt * 16) * 128u + r8 * 128u;
#pragma unroll
    for (int ng = 0; ng < 2; ++ng)
        bRow[ng] = (uint32_t)(wn * 32 + ng * 16) * 128u + r8 * 128u;

    // per-lane zz for the 8 owned rows: row = wm*64 + mt*16 + lane/4 (+8)
    float zzv[4][2];
#pragma unroll
    for (int mt = 0; mt < 4; ++mt) {
        zzv[mt][0] = zz_s[wm * 64 + mt * 16 + (lane >> 2)];
        zzv[mt][1] = zz_s[wm * 64 + mt * 16 + (lane >> 2) + 8];
    }

    float acc[4][4][4];
#pragma unroll
    for (int mt = 0; mt < 4; ++mt)
#pragma unroll
        for (int nt = 0; nt < 4; ++nt)
#pragma unroll
            for (int q = 0; q < 4; ++q) acc[mt][nt][q] = 0.0f;

    float bestd[4][2];
    int   besti[4][2];
#pragma unroll
    for (int mt = 0; mt < 4; ++mt)
#pragma unroll
        for (int h = 0; h < 2; ++h) {
            bestd[mt][h] = __int_as_float(0x7f800000);
            besti[mt][h] = 0;
        }

    // split products: hh, hr, rh  (rr dropped, ~2^-22 relative)
    const int PA[3] = {0, 0, 1};
    const int PB[3] = {0, 1, 0};

    for (int chunk = 0; chunk < NCHUNKS; ++chunk) {
        const int buf = chunk & 1;
        if (chunk + 1 < NCHUNKS) load_B_chunk(sb, chunk + 1, buf ^ 1, tid);
        CP_COMMIT();
        if (chunk + 1 < NCHUNKS) CP_WAIT(1); else CP_WAIT(0);
        __syncthreads();

        // ---- GEMM: 3 split products x 4 k-tiles over this 128-col chunk ----
#pragma unroll
        for (int p = 0; p < 3; ++p) {
            const uint32_t aB = sb + A_OFF + (uint32_t)PA[p] * 16384u;
            const uint32_t bB = sb + B_OFF + (uint32_t)(buf * 2 + PB[p]) * 16384u;
#pragma unroll
            for (int kt = 0; kt < 4; ++kt) {
                const uint32_t kc = ((uint32_t)(kt * 32) + colSel) ^ xm;
                uint32_t afr[4][4];
#pragma unroll
                for (int mt = 0; mt < 4; ++mt) ldsm_x4(afr[mt], aB + aRow[mt] + kc);
                uint32_t bfr[2][4];
#pragma unroll
                for (int ng = 0; ng < 2; ++ng) ldsm_x4(bfr[ng], bB + bRow[ng] + kc);
#pragma unroll
                for (int mt = 0; mt < 4; ++mt)
#pragma unroll
                    for (int nt = 0; nt < 4; ++nt)
                        mma_f16(acc[mt][nt], afr[mt],
                                bfr[nt >> 1][nt & 1], bfr[nt >> 1][(nt & 1) + 2]);
            }
        }

        // ---- fused argmin epilogue for this chunk, then reset acc ----
        const int colbase = chunk * CHUNK_N + wn * 32 + 2 * (lane & 3);
#pragma unroll
        for (int mt = 0; mt < 4; ++mt) {
#pragma unroll
            for (int nt = 0; nt < 4; ++nt) {
                const int c0 = colbase + nt * 8;
                const float cv0 = cs[c0], cv1 = cs[c0 + 1];
#pragma unroll
                for (int h = 0; h < 2; ++h) {
                    float d0 = __fsub_rn(__fadd_rn(zzv[mt][h], cv0),
                                         __fmul_rn(2.0f, acc[mt][nt][2 * h + 0]));
                    float d1 = __fsub_rn(__fadd_rn(zzv[mt][h], cv1),
                                         __fmul_rn(2.0f, acc[mt][nt][2 * h + 1]));
                    besti[mt][h] = (d0 < bestd[mt][h]) ? c0 : besti[mt][h];
                    bestd[mt][h] = fminf(bestd[mt][h], d0);
                    besti[mt][h] = (d1 < bestd[mt][h]) ? (c0 + 1) : besti[mt][h];
                    bestd[mt][h] = fminf(bestd[mt][h], d1);
                    acc[mt][nt][2 * h + 0] = 0.0f;
                    acc[mt][nt][2 * h + 1] = 0.0f;
                }
            }
        }

        __syncthreads();   // compute done before next iter overwrites buf
    }

    // ---- cross-lane / cross-warp argmin reduction ----
#pragma unroll
    for (int mt = 0; mt < 4; ++mt)
#pragma unroll
        for (int h = 0; h < 2; ++h) {
            float d = bestd[mt][h];
            int   i = besti[mt][h];
#pragma unroll
            for (int off = 1; off < 4; off <<= 1) {
                float od = __shfl_xor_sync(0xffffffffu, d, off);
                int   oi = __shfl_xor_sync(0xffffffffu, i, off);
                if (od < d || (od == d && oi < i)) { d = od; i = oi; }
            }
            if ((lane & 3) == 0) {
                int row = wm * 64 + mt * 16 + (lane >> 2) + 8 * h;
                red_d[row * 4 + wn] = d;
                red_i[row * 4 + wn] = i;
            }
        }
    __syncthreads();

    if (tid < 128) {
        float bd = red_d[tid * 4 + 0];
        int   bi = red_i[tid * 4 + 0];
#pragma unroll
        for (int w = 1; w < 4; ++w) {
            float d = red_d[tid * 4 + w];
            int   i = red_i[tid * 4 + w];
            if (d < bd || (d == bd && i < bi)) { bd = d; bi = i; }
        }
        args[tid] = bi;
    }
    __syncthreads();

    // ---- one-hot: write full rows, streaming (evict-first) ----
    for (int i = tid; i < 128 * (KCB / 4); i += 256) {
        int r  = i >> 9;          // /512
        int c4 = i & 511;
        float4 v = make_float4(0.f, 0.f, 0.f, 0.f);
        int a = args[r];
        if ((a >> 2) == c4) ((float*)&v)[a & 3] = 1.0f;
        __stcs((float4*)(outOH + (size_t)(row0 + r) * KCB) + c4, v);
    }

    // ---- quantized gather: 128 rows x 32 float4 ----
    {
        const float4* e4 = (const float4*)emb;
        for (int i = tid; i < 128 * 32; i += 256) {
            int r = i >> 5, c = i & 31;
            float4 v = __ldg(e4 + (size_t)args[r] * 32 + c);
            __stcs((float4*)outQ + (size_t)(row0 + r) * 32 + c, v);
        }
    }
}

// ============================================================================
// Launch
// ============================================================================
extern "C" void kernel_launch(void* const* d_in, const int* in_sizes, int n_in,
                              void* d_out, int out_size) {
    const float* z   = (const float*)d_in[0];
    const float* W   = (const float*)d_in[1];
    const float* b   = (const float*)d_in[2];
    const float* emb = (const float*)d_in[3];

    float* outQ  = (float*)d_out;                 // [N, 128]
    float* outOH = outQ + (size_t)NROWS * DDIM;   // [N, 2048]

    cudaFuncSetAttribute(prep_kernel, cudaFuncAttributeMaxDynamicSharedMemorySize, PREP_SMEM);
    cudaFuncSetAttribute(vq_main_kernel, cudaFuncAttributeMaxDynamicSharedMemorySize, MAIN_SMEM);

    prep_kernel<<<KCB / 64, 256, PREP_SMEM>>>(emb, W, b, 1);
    prep_kernel<<<NROWS / 64, 256, PREP_SMEM>>>(z, W, b, 0);
    vq_main_kernel<<<NTILES, 256, MAIN_SMEM>>>(emb, outQ, outOH);
}